// round 1
// baseline (speedup 1.0000x reference)
#include <cuda_runtime.h>
#include <math.h>

#define T_TOK 8192
#define CDIM  1024
#define HDIM  4096
#define NEXP  8
#define TM    128
#define MAXTILES 136            // max sum of ceil(cnt_e/128) = 128 + 7
#define HROWS_MAX (MAXTILES * TM)

// ---------------- scratch (device globals; no runtime allocation) ----------------
__device__ int   g_cnt[NEXP];
__device__ int   g_off[NEXP];
__device__ int   g_tok[NEXP * T_TOK];
__device__ float g_wt [NEXP * T_TOK];
__device__ int   g_tile_e[MAXTILES];
__device__ int   g_tile_l[MAXTILES];
__device__ int   g_ntiles;
__device__ float g_H[(size_t)HROWS_MAX * HDIM];   // ~285 MB intermediate activations

// ---------------- helpers ----------------
__device__ __forceinline__ unsigned int f2tf32(float f) {
    unsigned int r;
    asm("cvt.rna.tf32.f32 %0, %1;" : "=r"(r) : "f"(f));
    return r;
}

__device__ __forceinline__ void mma_tf32(float c[4], const unsigned int a[4],
                                         const unsigned int b[2]) {
    asm volatile(
        "mma.sync.aligned.m16n8k8.row.col.f32.tf32.tf32.f32 "
        "{%0,%1,%2,%3}, {%4,%5,%6,%7}, {%8,%9}, {%0,%1,%2,%3};"
        : "+f"(c[0]), "+f"(c[1]), "+f"(c[2]), "+f"(c[3])
        : "r"(a[0]), "r"(a[1]), "r"(a[2]), "r"(a[3]), "r"(b[0]), "r"(b[1]));
}

__device__ __forceinline__ float gelu_tanh(float v) {
    // jax.nn.gelu default: approximate=True (tanh form)
    float u = v + 0.044715f * v * v * v;
    return 0.5f * v * (1.0f + tanhf(0.7978845608028654f * u));
}

// ---------------- kernels ----------------
__global__ void reset_kernel() {
    if (threadIdx.x < NEXP) g_cnt[threadIdx.x] = 0;
}

// One block per token: logits, softmax, top-2, normalized weights, list append.
__global__ void router_kernel(const float* __restrict__ x,
                              const float* __restrict__ gw) {
    __shared__ float xs[CDIM];
    __shared__ float lg[NEXP];
    const int t   = blockIdx.x;
    const int tid = threadIdx.x;

    // stage token row in smem (256 threads x float4 = 1024 floats)
    ((float4*)xs)[tid] = ((const float4*)(x + (size_t)t * CDIM))[tid];
    __syncthreads();

    const int e = tid >> 5, lane = tid & 31;
    const float* w = gw + e * CDIM;
    float s = 0.f;
    for (int i = lane * 4; i < CDIM; i += 128) {
        float4 a = *(const float4*)(xs + i);
        float4 b = *(const float4*)(w + i);
        s += a.x * b.x + a.y * b.y + a.z * b.z + a.w * b.w;
    }
    #pragma unroll
    for (int o = 16; o; o >>= 1) s += __shfl_xor_sync(0xffffffffu, s, o);
    if (lane == 0) lg[e] = s;
    __syncthreads();

    if (tid == 0) {
        float m = lg[0];
        #pragma unroll
        for (int i = 1; i < NEXP; i++) m = fmaxf(m, lg[i]);
        float p[NEXP]; float S = 0.f;
        #pragma unroll
        for (int i = 0; i < NEXP; i++) { p[i] = expf(lg[i] - m); S += p[i]; }
        #pragma unroll
        for (int i = 0; i < NEXP; i++) p[i] /= S;
        int i1 = 0;
        #pragma unroll
        for (int i = 1; i < NEXP; i++) if (p[i] > p[i1]) i1 = i;
        int i2 = (i1 == 0) ? 1 : 0;
        #pragma unroll
        for (int i = 0; i < NEXP; i++) { if (i == i1) continue; if (p[i] > p[i2]) i2 = i; }
        float denom = p[i1] + p[i2] + 1e-8f;
        float wa = p[i1] / denom, wb = p[i2] / denom;
        int pos = atomicAdd(&g_cnt[i1], 1);
        g_tok[i1 * T_TOK + pos] = t; g_wt[i1 * T_TOK + pos] = wa;
        pos = atomicAdd(&g_cnt[i2], 1);
        g_tok[i2 * T_TOK + pos] = t; g_wt[i2 * T_TOK + pos] = wb;
    }
}

__global__ void sched_kernel() {
    if (threadIdx.x == 0) {
        int acc = 0, nt = 0;
        for (int e = 0; e < NEXP; e++) {
            g_off[e] = acc;
            int c = g_cnt[e];
            int k = (c + TM - 1) / TM;
            for (int i = 0; i < k; i++) { g_tile_e[nt] = e; g_tile_l[nt] = i; nt++; }
            acc += k * TM;
        }
        g_ntiles = nt;
    }
}

// Grouped GEMM: C[128x128] tile per block over K, tf32 HMMA, fp32 accum.
// FFN1: A = gathered x rows, epilogue = gelu(acc + b1) -> g_H
// FFN2: A = g_H rows,        epilogue = atomicAdd(out, wt*(acc + b2))
template <int KDIM, bool FFN1>
__global__ void __launch_bounds__(256) ffn_gemm(const float* __restrict__ Aglb,
                                                const float* __restrict__ Bglb,
                                                const float* __restrict__ bias,
                                                float* __restrict__ outp) {
    const int tile = blockIdx.x;
    if (tile >= g_ntiles) return;
    const int e     = g_tile_e[tile];
    const int l     = g_tile_l[tile];
    const int cnt   = g_cnt[e];
    const int r0    = l * TM;
    const int valid = min(TM, cnt - r0);
    const int NB    = FFN1 ? HDIM : CDIM;
    const int n0    = blockIdx.y * 128;
    const float* Bexp = Bglb + (size_t)e * KDIM * NB;
    const float* be   = bias + e * NB;
    const int hbase   = g_off[e] + r0;

    __shared__ unsigned int As[128][20];   // stride 20 words: conflict-free frag reads
    __shared__ unsigned int Bs[128][20];
    __shared__ int   tok_s[128];
    __shared__ float wt_s[128];

    const int tid = threadIdx.x;
    if (tid < 128) {
        bool v = tid < valid;
        int idx = e * T_TOK + r0 + tid;
        tok_s[tid] = v ? g_tok[idx] : 0;
        wt_s[tid]  = v ? g_wt[idx]  : 0.f;
    }
    __syncthreads();

    const int wid = tid >> 5, lane = tid & 31;
    const int g = lane >> 2, tg = lane & 3;
    const int wm = (wid & 3) * 32;     // warp row offset in tile
    const int wn = (wid >> 2) * 64;    // warp col offset in tile

    float acc[2][8][4];
    #pragma unroll
    for (int i = 0; i < 2; i++)
        #pragma unroll
        for (int j = 0; j < 8; j++)
            #pragma unroll
            for (int q = 0; q < 4; q++) acc[i][j][q] = 0.f;

    for (int kc = 0; kc < KDIM; kc += 16) {
        // A tile: 128 rows x 16 cols = 512 float4 loads
        #pragma unroll
        for (int it = 0; it < 2; it++) {
            int tt = tid + it * 256;
            int row = tt >> 2, q = tt & 3;
            const float* ap;
            if (FFN1) ap = Aglb + (size_t)tok_s[row] * CDIM + kc + q * 4;
            else      ap = g_H + (size_t)(hbase + row) * HDIM + kc + q * 4;
            float4 v = *(const float4*)ap;
            As[row][q * 4 + 0] = f2tf32(v.x);
            As[row][q * 4 + 1] = f2tf32(v.y);
            As[row][q * 4 + 2] = f2tf32(v.z);
            As[row][q * 4 + 3] = f2tf32(v.w);
        }
        // B tile
        #pragma unroll
        for (int it = 0; it < 2; it++) {
            int tt = tid + it * 256;
            int row = tt >> 2, q = tt & 3;
            const float* bp = Bexp + (size_t)(n0 + row) * KDIM + kc + q * 4;
            float4 v = *(const float4*)bp;
            Bs[row][q * 4 + 0] = f2tf32(v.x);
            Bs[row][q * 4 + 1] = f2tf32(v.y);
            Bs[row][q * 4 + 2] = f2tf32(v.z);
            Bs[row][q * 4 + 3] = f2tf32(v.w);
        }
        __syncthreads();

        #pragma unroll
        for (int ks = 0; ks < 16; ks += 8) {
            unsigned int af[2][4];
            #pragma unroll
            for (int i = 0; i < 2; i++) {
                int mb = wm + i * 16;
                af[i][0] = As[mb + g    ][ks + tg];
                af[i][1] = As[mb + g + 8][ks + tg];
                af[i][2] = As[mb + g    ][ks + tg + 4];
                af[i][3] = As[mb + g + 8][ks + tg + 4];
            }
            unsigned int bf[8][2];
            #pragma unroll
            for (int j = 0; j < 8; j++) {
                int nb = wn + j * 8 + g;
                bf[j][0] = Bs[nb][ks + tg];
                bf[j][1] = Bs[nb][ks + tg + 4];
            }
            #pragma unroll
            for (int i = 0; i < 2; i++)
                #pragma unroll
                for (int j = 0; j < 8; j++)
                    mma_tf32(acc[i][j], af[i], bf[j]);
        }
        __syncthreads();
    }

    // epilogue
    #pragma unroll
    for (int i = 0; i < 2; i++) {
        const int mloc0 = wm + i * 16 + g;
        #pragma unroll
        for (int half = 0; half < 2; half++) {
            const int r = mloc0 + half * 8;
            if (r < valid) {
                #pragma unroll
                for (int j = 0; j < 8; j++) {
                    const int n = n0 + wn + j * 8 + tg * 2;
                    float v0 = acc[i][j][half * 2 + 0] + be[n];
                    float v1 = acc[i][j][half * 2 + 1] + be[n + 1];
                    if (FFN1) {
                        float* hp = g_H + (size_t)(hbase + r) * HDIM + n;
                        hp[0] = gelu_tanh(v0);
                        hp[1] = gelu_tanh(v1);
                    } else {
                        const int token = tok_s[r];
                        const float w = wt_s[r];
                        float* op = outp + (size_t)token * CDIM + n;
                        atomicAdd(op,     w * v0);
                        atomicAdd(op + 1, w * v1);
                    }
                }
            }
        }
    }
}

// ---------------- launch ----------------
extern "C" void kernel_launch(void* const* d_in, const int* in_sizes, int n_in,
                              void* d_out, int out_size) {
    const float* x  = (const float*)d_in[0];
    const float* gw = (const float*)d_in[1];
    const float* w1 = (const float*)d_in[2];
    const float* b1 = (const float*)d_in[3];
    const float* w2 = (const float*)d_in[4];
    const float* b2 = (const float*)d_in[5];
    float* out = (float*)d_out;

    cudaMemsetAsync(out, 0, (size_t)T_TOK * CDIM * sizeof(float));
    reset_kernel<<<1, 32>>>();
    router_kernel<<<T_TOK, 256>>>(x, gw);
    sched_kernel<<<1, 32>>>();
    ffn_gemm<CDIM, true ><<<dim3(MAXTILES, HDIM / 128), 256>>>(x,       w1, b1, nullptr);
    ffn_gemm<HDIM, false><<<dim3(MAXTILES, CDIM / 128), 256>>>(nullptr, w2, b2, out);
}

// round 2
// speedup vs baseline: 1.1570x; 1.1570x over previous
#include <cuda_runtime.h>
#include <math.h>

#define T_TOK 8192
#define CDIM  1024
#define HDIM  4096
#define NEXP  8
#define TM    128
#define MAXTILES 136            // max sum of ceil(cnt_e/128) = 128 + 7
#define HROWS_MAX (MAXTILES * TM)

// ---------------- scratch (device globals; no runtime allocation) ----------------
__device__ int   g_cnt[NEXP];
__device__ int   g_off[NEXP];
__device__ int   g_tok[NEXP * T_TOK];
__device__ float g_wt [NEXP * T_TOK];
__device__ int   g_tile_e[MAXTILES];
__device__ int   g_tile_l[MAXTILES];
__device__ int   g_ntiles;
__device__ float g_H[(size_t)HROWS_MAX * HDIM];   // ~285 MB intermediate activations

// ---------------- helpers ----------------
__device__ __forceinline__ unsigned int f2tf32(float f) {
    unsigned int r;
    asm("cvt.rna.tf32.f32 %0, %1;" : "=r"(r) : "f"(f));
    return r;
}

__device__ __forceinline__ void mma_tf32(float c[4], unsigned int a0, unsigned int a1,
                                         unsigned int a2, unsigned int a3,
                                         unsigned int b0, unsigned int b1) {
    asm volatile(
        "mma.sync.aligned.m16n8k8.row.col.f32.tf32.tf32.f32 "
        "{%0,%1,%2,%3}, {%4,%5,%6,%7}, {%8,%9}, {%0,%1,%2,%3};"
        : "+f"(c[0]), "+f"(c[1]), "+f"(c[2]), "+f"(c[3])
        : "r"(a0), "r"(a1), "r"(a2), "r"(a3), "r"(b0), "r"(b1));
}

__device__ __forceinline__ float gelu_tanh(float v) {
    float u = v + 0.044715f * v * v * v;
    return 0.5f * v * (1.0f + tanhf(0.7978845608028654f * u));
}

// ---------------- kernels ----------------
__global__ void reset_kernel() {
    if (threadIdx.x < NEXP) g_cnt[threadIdx.x] = 0;
}

__global__ void router_kernel(const float* __restrict__ x,
                              const float* __restrict__ gw) {
    __shared__ float xs[CDIM];
    __shared__ float lg[NEXP];
    const int t   = blockIdx.x;
    const int tid = threadIdx.x;

    ((float4*)xs)[tid] = ((const float4*)(x + (size_t)t * CDIM))[tid];
    __syncthreads();

    const int e = tid >> 5, lane = tid & 31;
    const float* w = gw + e * CDIM;
    float s = 0.f;
    for (int i = lane * 4; i < CDIM; i += 128) {
        float4 a = *(const float4*)(xs + i);
        float4 b = *(const float4*)(w + i);
        s += a.x * b.x + a.y * b.y + a.z * b.z + a.w * b.w;
    }
    #pragma unroll
    for (int o = 16; o; o >>= 1) s += __shfl_xor_sync(0xffffffffu, s, o);
    if (lane == 0) lg[e] = s;
    __syncthreads();

    if (tid == 0) {
        float m = lg[0];
        #pragma unroll
        for (int i = 1; i < NEXP; i++) m = fmaxf(m, lg[i]);
        float p[NEXP]; float S = 0.f;
        #pragma unroll
        for (int i = 0; i < NEXP; i++) { p[i] = expf(lg[i] - m); S += p[i]; }
        #pragma unroll
        for (int i = 0; i < NEXP; i++) p[i] /= S;
        int i1 = 0;
        #pragma unroll
        for (int i = 1; i < NEXP; i++) if (p[i] > p[i1]) i1 = i;
        int i2 = (i1 == 0) ? 1 : 0;
        #pragma unroll
        for (int i = 0; i < NEXP; i++) { if (i == i1) continue; if (p[i] > p[i2]) i2 = i; }
        float denom = p[i1] + p[i2] + 1e-8f;
        float wa = p[i1] / denom, wb = p[i2] / denom;
        int pos = atomicAdd(&g_cnt[i1], 1);
        g_tok[i1 * T_TOK + pos] = t; g_wt[i1 * T_TOK + pos] = wa;
        pos = atomicAdd(&g_cnt[i2], 1);
        g_tok[i2 * T_TOK + pos] = t; g_wt[i2 * T_TOK + pos] = wb;
    }
}

__global__ void sched_kernel() {
    if (threadIdx.x == 0) {
        int acc = 0, nt = 0;
        for (int e = 0; e < NEXP; e++) {
            g_off[e] = acc;
            int c = g_cnt[e];
            int k = (c + TM - 1) / TM;
            for (int i = 0; i < k; i++) { g_tile_e[nt] = e; g_tile_l[nt] = i; nt++; }
            acc += k * TM;
        }
        g_ntiles = nt;
    }
}

// Grouped GEMM: C[128x128] tile per block, tf32 HMMA fp32 accum.
// Double-buffered smem (reg-staged), permuted smem layout for LDS.128 fragments.
// smem word layout per row (16 k-words): pos = ((k&3)^(row&3))*4 + (k>>2)
template <int KDIM, bool FFN1>
__global__ void __launch_bounds__(256, 2) ffn_gemm(const float* __restrict__ Aglb,
                                                   const float* __restrict__ Bglb,
                                                   const float* __restrict__ bias,
                                                   float* __restrict__ outp) {
    const int tile = blockIdx.x;
    if (tile >= g_ntiles) return;
    const int e     = g_tile_e[tile];
    const int l     = g_tile_l[tile];
    const int cnt   = g_cnt[e];
    const int r0    = l * TM;
    const int valid = min(TM, cnt - r0);
    const int NB    = FFN1 ? HDIM : CDIM;
    const int n0    = blockIdx.y * 128;
    const float* Bexp = Bglb + (size_t)e * KDIM * NB;
    const float* be   = bias + e * NB;
    const int hbase   = g_off[e] + r0;

    __shared__ unsigned int As[2][128 * 16];
    __shared__ unsigned int Bs[2][128 * 16];
    __shared__ int   tok_s[128];
    __shared__ float wt_s[128];

    const int tid = threadIdx.x;
    if (tid < 128) {
        bool v = tid < valid;
        int idx = e * T_TOK + r0 + tid;
        tok_s[tid] = v ? g_tok[idx] : 0;
        wt_s[tid]  = v ? g_wt[idx]  : 0.f;
    }
    __syncthreads();

    // -------- staging setup (each thread owns 2 A-float4s and 2 B-float4s) --------
    const int rowA0 = tid >> 2, rowA1 = rowA0 + 64;
    const int q     = tid & 3;
    const float* aP0;
    const float* aP1;
    if (FFN1) {
        aP0 = Aglb + (size_t)tok_s[rowA0] * CDIM + q * 4;
        aP1 = Aglb + (size_t)tok_s[rowA1] * CDIM + q * 4;
    } else {
        aP0 = g_H + (size_t)(hbase + rowA0) * HDIM + q * 4;
        aP1 = g_H + (size_t)(hbase + rowA1) * HDIM + q * 4;
    }
    const float* bP0 = Bexp + (size_t)(n0 + rowA0) * KDIM + q * 4;
    const float* bP1 = Bexp + (size_t)(n0 + rowA1) * KDIM + q * 4;

    // precomputed permuted store offsets: pos(row,j) = ((j^(row&3))<<2) + q
    const int rA0x = rowA0 & 3, rA1x = rowA1 & 3;
    const int sA0 = rowA0 * 16, sA1 = rowA1 * 16;

    float4 va0, va1, vb0, vb1;

    #define LDG_TILE(kc)  do { va0 = *(const float4*)(aP0 + (kc)); \
                               va1 = *(const float4*)(aP1 + (kc)); \
                               vb0 = *(const float4*)(bP0 + (kc)); \
                               vb1 = *(const float4*)(bP1 + (kc)); } while (0)

    #define STS_TILE(buf) do { \
        unsigned int* a_ = As[buf]; unsigned int* b_ = Bs[buf]; \
        a_[sA0 + (((0^rA0x)<<2) + q)] = f2tf32(va0.x); \
        a_[sA0 + (((1^rA0x)<<2) + q)] = f2tf32(va0.y); \
        a_[sA0 + (((2^rA0x)<<2) + q)] = f2tf32(va0.z); \
        a_[sA0 + (((3^rA0x)<<2) + q)] = f2tf32(va0.w); \
        a_[sA1 + (((0^rA1x)<<2) + q)] = f2tf32(va1.x); \
        a_[sA1 + (((1^rA1x)<<2) + q)] = f2tf32(va1.y); \
        a_[sA1 + (((2^rA1x)<<2) + q)] = f2tf32(va1.z); \
        a_[sA1 + (((3^rA1x)<<2) + q)] = f2tf32(va1.w); \
        b_[sA0 + (((0^rA0x)<<2) + q)] = f2tf32(vb0.x); \
        b_[sA0 + (((1^rA0x)<<2) + q)] = f2tf32(vb0.y); \
        b_[sA0 + (((2^rA0x)<<2) + q)] = f2tf32(vb0.z); \
        b_[sA0 + (((3^rA0x)<<2) + q)] = f2tf32(vb0.w); \
        b_[sA1 + (((0^rA1x)<<2) + q)] = f2tf32(vb1.x); \
        b_[sA1 + (((1^rA1x)<<2) + q)] = f2tf32(vb1.y); \
        b_[sA1 + (((2^rA1x)<<2) + q)] = f2tf32(vb1.z); \
        b_[sA1 + (((3^rA1x)<<2) + q)] = f2tf32(vb1.w); } while (0)

    // -------- MMA setup --------
    const int wid = tid >> 5, lane = tid & 31;
    const int g = lane >> 2, tg = lane & 3;
    const int wm = (wid & 3) * 32;
    const int wn = (wid >> 2) * 64;
    const int swz = ((tg ^ (g & 3)) << 2);   // same for all rows we touch (row&3 == g&3)

    float acc[2][8][4];
    #pragma unroll
    for (int i = 0; i < 2; i++)
        #pragma unroll
        for (int j = 0; j < 8; j++)
            #pragma unroll
            for (int p_ = 0; p_ < 4; p_++) acc[i][j][p_] = 0.f;

    LDG_TILE(0);
    STS_TILE(0);
    __syncthreads();

    int cur = 0;
    for (int kc = 0; kc < KDIM; kc += 16) {
        const bool has_next = (kc + 16) < KDIM;
        if (has_next) LDG_TILE(kc + 16);

        const unsigned int* Ab = As[cur];
        const unsigned int* Bb = Bs[cur];

        uint4 aF[2][2];
        #pragma unroll
        for (int i = 0; i < 2; i++) {
            const int r1 = wm + i * 16 + g;
            aF[i][0] = *(const uint4*)(Ab + r1 * 16 + swz);
            aF[i][1] = *(const uint4*)(Ab + (r1 + 8) * 16 + swz);
        }
        #pragma unroll
        for (int j = 0; j < 8; j++) {
            const int nb = wn + j * 8 + g;
            uint4 bF = *(const uint4*)(Bb + nb * 16 + swz);
            #pragma unroll
            for (int i = 0; i < 2; i++) {
                mma_tf32(acc[i][j], aF[i][0].x, aF[i][1].x, aF[i][0].y, aF[i][1].y,
                         bF.x, bF.y);
                mma_tf32(acc[i][j], aF[i][0].z, aF[i][1].z, aF[i][0].w, aF[i][1].w,
                         bF.z, bF.w);
            }
        }

        if (has_next) {
            STS_TILE(cur ^ 1);
            __syncthreads();
        }
        cur ^= 1;
    }

    // -------- epilogue --------
    #pragma unroll
    for (int i = 0; i < 2; i++) {
        const int mloc0 = wm + i * 16 + g;
        #pragma unroll
        for (int half = 0; half < 2; half++) {
            const int r = mloc0 + half * 8;
            if (r < valid) {
                #pragma unroll
                for (int j = 0; j < 8; j++) {
                    const int n = n0 + wn + j * 8 + tg * 2;
                    float v0 = acc[i][j][half * 2 + 0] + be[n];
                    float v1 = acc[i][j][half * 2 + 1] + be[n + 1];
                    if (FFN1) {
                        float* hp = g_H + (size_t)(hbase + r) * HDIM + n;
                        hp[0] = gelu_tanh(v0);
                        hp[1] = gelu_tanh(v1);
                    } else {
                        const int token = tok_s[r];
                        const float w = wt_s[r];
                        float* op = outp + (size_t)token * CDIM + n;
                        atomicAdd(op,     w * v0);
                        atomicAdd(op + 1, w * v1);
                    }
                }
            }
        }
    }
    #undef LDG_TILE
    #undef STS_TILE
}

// ---------------- launch ----------------
extern "C" void kernel_launch(void* const* d_in, const int* in_sizes, int n_in,
                              void* d_out, int out_size) {
    const float* x  = (const float*)d_in[0];
    const float* gw = (const float*)d_in[1];
    const float* w1 = (const float*)d_in[2];
    const float* b1 = (const float*)d_in[3];
    const float* w2 = (const float*)d_in[4];
    const float* b2 = (const float*)d_in[5];
    float* out = (float*)d_out;

    cudaMemsetAsync(out, 0, (size_t)T_TOK * CDIM * sizeof(float));
    reset_kernel<<<1, 32>>>();
    router_kernel<<<T_TOK, 256>>>(x, gw);
    sched_kernel<<<1, 32>>>();
    ffn_gemm<CDIM, true ><<<dim3(MAXTILES, HDIM / 128), 256>>>(x,       w1, b1, nullptr);
    ffn_gemm<HDIM, false><<<dim3(MAXTILES, CDIM / 128), 256>>>(nullptr, w2, b2, out);
}

// round 5
// speedup vs baseline: 1.3726x; 1.1863x over previous
#include <cuda_runtime.h>
#include <math.h>
#include <stdint.h>

#define T_TOK 8192
#define CDIM  1024
#define HDIM  4096
#define NEXP  8
#define TM    128
#define MAXTILES 136
#define HROWS_MAX (MAXTILES * TM)
#define NSTAGE 4
#define KSTG   16
#define STG_BYTES (TM * KSTG * 4)            // 8192 per operand per stage

// ---------------- device scratch ----------------
__device__ int   g_cnt[NEXP];
__device__ int   g_off[NEXP];
__device__ int   g_tok[NEXP * T_TOK];
__device__ float g_wt [NEXP * T_TOK];
__device__ int   g_tile_e[MAXTILES];
__device__ int   g_tile_l[MAXTILES];
__device__ int   g_ntiles;
__device__ float g_X[(size_t)HROWS_MAX * CDIM];      // gathered x, tf32-rounded
__device__ float g_H[(size_t)HROWS_MAX * HDIM];      // activations, tf32-rounded
__device__ float g_W1[(size_t)NEXP * HDIM * CDIM];   // tf32-rounded weights
__device__ float g_W2[(size_t)NEXP * CDIM * HDIM];

// ---------------- helpers ----------------
__device__ __forceinline__ unsigned int f2tf32(float f) {
    unsigned int r;
    asm("cvt.rna.tf32.f32 %0, %1;" : "=r"(r) : "f"(f));
    return r;
}
__device__ __forceinline__ float rna_tf32(float f) { return __uint_as_float(f2tf32(f)); }

__device__ __forceinline__ uint32_t smem_u32(const void* p) {
    uint32_t a;
    asm("{ .reg .u64 t; cvta.to.shared.u64 t, %1; cvt.u32.u64 %0, t; }" : "=r"(a) : "l"(p));
    return a;
}
__device__ __forceinline__ void cpasync16(uint32_t dst, const float* src) {
    asm volatile("cp.async.cg.shared.global [%0], [%1], 16;" :: "r"(dst), "l"(src));
}
#define CP_COMMIT()  asm volatile("cp.async.commit_group;" ::: "memory")
#define CP_WAIT(n)   asm volatile("cp.async.wait_group %0;" :: "n"(n) : "memory")

__device__ __forceinline__ void mma_tf32(float c[4], unsigned int a0, unsigned int a1,
                                         unsigned int a2, unsigned int a3,
                                         unsigned int b0, unsigned int b1) {
    asm volatile(
        "mma.sync.aligned.m16n8k8.row.col.f32.tf32.tf32.f32 "
        "{%0,%1,%2,%3}, {%4,%5,%6,%7}, {%8,%9}, {%0,%1,%2,%3};"
        : "+f"(c[0]), "+f"(c[1]), "+f"(c[2]), "+f"(c[3])
        : "r"(a0), "r"(a1), "r"(a2), "r"(a3), "r"(b0), "r"(b1));
}

__device__ __forceinline__ float gelu_tanh(float v) {
    float u = v + 0.044715f * v * v * v;
    return 0.5f * v * (1.0f + tanhf(0.7978845608028654f * u));
}

// ---------------- small kernels ----------------
__global__ void reset_kernel() {
    if (threadIdx.x < NEXP) g_cnt[threadIdx.x] = 0;
}

__global__ void router_kernel(const float* __restrict__ x,
                              const float* __restrict__ gw) {
    __shared__ float xs[CDIM];
    __shared__ float lg[NEXP];
    const int t = blockIdx.x, tid = threadIdx.x;
    ((float4*)xs)[tid] = ((const float4*)(x + (size_t)t * CDIM))[tid];
    __syncthreads();
    const int e = tid >> 5, lane = tid & 31;
    const float* w = gw + e * CDIM;
    float s = 0.f;
    for (int i = lane * 4; i < CDIM; i += 128) {
        float4 a = *(const float4*)(xs + i);
        float4 b = *(const float4*)(w + i);
        s += a.x * b.x + a.y * b.y + a.z * b.z + a.w * b.w;
    }
    #pragma unroll
    for (int o = 16; o; o >>= 1) s += __shfl_xor_sync(0xffffffffu, s, o);
    if (lane == 0) lg[e] = s;
    __syncthreads();
    if (tid == 0) {
        float m = lg[0];
        #pragma unroll
        for (int i = 1; i < NEXP; i++) m = fmaxf(m, lg[i]);
        float p[NEXP]; float S = 0.f;
        #pragma unroll
        for (int i = 0; i < NEXP; i++) { p[i] = expf(lg[i] - m); S += p[i]; }
        #pragma unroll
        for (int i = 0; i < NEXP; i++) p[i] /= S;
        int i1 = 0;
        #pragma unroll
        for (int i = 1; i < NEXP; i++) if (p[i] > p[i1]) i1 = i;
        int i2 = (i1 == 0) ? 1 : 0;
        #pragma unroll
        for (int i = 0; i < NEXP; i++) { if (i == i1) continue; if (p[i] > p[i2]) i2 = i; }
        float denom = p[i1] + p[i2] + 1e-8f;
        float wa = p[i1] / denom, wb = p[i2] / denom;
        int pos = atomicAdd(&g_cnt[i1], 1);
        g_tok[i1 * T_TOK + pos] = t; g_wt[i1 * T_TOK + pos] = wa;
        pos = atomicAdd(&g_cnt[i2], 1);
        g_tok[i2 * T_TOK + pos] = t; g_wt[i2 * T_TOK + pos] = wb;
    }
}

__global__ void sched_kernel() {
    if (threadIdx.x == 0) {
        int acc = 0, nt = 0;
        for (int e = 0; e < NEXP; e++) {
            g_off[e] = acc;
            int c = g_cnt[e];
            int k = (c + TM - 1) / TM;
            for (int i = 0; i < k; i++) { g_tile_e[nt] = e; g_tile_l[nt] = i; nt++; }
            acc += k * TM;
        }
        g_ntiles = nt;
    }
}

// gather + rna-round x rows into padded per-expert segments (zero padding)
__global__ void gather_kernel(const float* __restrict__ x) {
    const int row = blockIdx.x;
    const int tile = row >> 7;
    if (tile >= g_ntiles) return;
    const int e = g_tile_e[tile];
    const int local = g_tile_l[tile] * TM + (row & 127);
    float4* dst = (float4*)(g_X + (size_t)row * CDIM);
    if (local < g_cnt[e]) {
        const float4* src = (const float4*)(x + (size_t)g_tok[e * T_TOK + local] * CDIM);
        float4 v = src[threadIdx.x];
        v.x = rna_tf32(v.x); v.y = rna_tf32(v.y); v.z = rna_tf32(v.z); v.w = rna_tf32(v.w);
        dst[threadIdx.x] = v;
    } else {
        dst[threadIdx.x] = make_float4(0.f, 0.f, 0.f, 0.f);
    }
}

__global__ void convw1_kernel(const float* __restrict__ w) {
    size_t i = (size_t)blockIdx.x * 256 + threadIdx.x;
    float4 v = ((const float4*)w)[i];
    v.x = rna_tf32(v.x); v.y = rna_tf32(v.y); v.z = rna_tf32(v.z); v.w = rna_tf32(v.w);
    ((float4*)g_W1)[i] = v;
}
__global__ void convw2_kernel(const float* __restrict__ w) {
    size_t i = (size_t)blockIdx.x * 256 + threadIdx.x;
    float4 v = ((const float4*)w)[i];
    v.x = rna_tf32(v.x); v.y = rna_tf32(v.y); v.z = rna_tf32(v.z); v.w = rna_tf32(v.w);
    ((float4*)g_W2)[i] = v;
}

// ---------------- grouped GEMM, mma.sync tf32, cp.async pipeline ----------------
// Tile 128x128, 8 warps (4x2), warp tile 32x64. KSTG=16, NSTAGE=4.
// A/B sources are device globals referenced IN DEVICE CODE (host cannot take
// the address of a __device__ symbol — that was round 4's bug).
// smem: [0,1024) tok/wt | A stages 4x8KB | B stages 4x8KB  = 66560 B
#define FFN_SMEM (1024 + 2 * NSTAGE * STG_BYTES)

template <int KDIM, bool FFN1>
__global__ void __launch_bounds__(256, 2) ffn_gemm(const float* __restrict__ bias,
                                                   float* __restrict__ outp) {
    extern __shared__ char smem[];
    const int tile = blockIdx.x;
    if (tile >= g_ntiles) return;

    const float* Aglb = FFN1 ? g_X  : g_H;    // device-side symbol refs (valid)
    const float* Bglb = FFN1 ? g_W1 : g_W2;

    const int e     = g_tile_e[tile];
    const int l     = g_tile_l[tile];
    const int cnt   = g_cnt[e];
    const int r0    = l * TM;
    const int valid = min(TM, cnt - r0);
    const int NB    = FFN1 ? HDIM : CDIM;
    const int n0    = blockIdx.y * 128;
    const float* Bexp = Bglb + (size_t)e * KDIM * NB;
    const float* be   = bias + e * NB;
    const int hbase   = g_off[e] + r0;
    const int tid = threadIdx.x, wid = tid >> 5, lane = tid & 31;

    int*   tok_s = (int*)smem;
    float* wt_s  = (float*)(smem + 512);
    unsigned int* Asm = (unsigned int*)(smem + 1024);
    unsigned int* Bsm = (unsigned int*)(smem + 1024 + NSTAGE * STG_BYTES);
    const uint32_t Abase_u = smem_u32(Asm);
    const uint32_t Bbase_u = smem_u32(Bsm);

    if (tid < TM) {
        bool v = tid < valid;
        int idx = e * T_TOK + r0 + tid;
        tok_s[tid] = v ? g_tok[idx] : 0;
        wt_s[tid]  = v ? g_wt[idx]  : 0.f;
    }
    __syncthreads();

    // cp.async mapping: chunk c in [0,512): row=c>>2, cw=c&3. Thread owns c=tid, tid+256.
    const int c0 = tid, c1 = tid + 256;
    const float* aS0 = Aglb + (size_t)(hbase + (c0 >> 2)) * KDIM + (c0 & 3) * 4;
    const float* aS1 = Aglb + (size_t)(hbase + (c1 >> 2)) * KDIM + (c1 & 3) * 4;
    const float* bS0 = Bexp + (size_t)(n0 + (c0 >> 2)) * KDIM + (c0 & 3) * 4;
    const float* bS1 = Bexp + (size_t)(n0 + (c1 >> 2)) * KDIM + (c1 & 3) * 4;
    const uint32_t aD0 = Abase_u + c0 * 16, aD1 = Abase_u + c1 * 16;
    const uint32_t bD0 = Bbase_u + c0 * 16, bD1 = Bbase_u + c1 * 16;

    #define PRODUCE(t) do { \
        const int _b = (t) & (NSTAGE - 1); \
        const int _k = (t) * KSTG; \
        const uint32_t _o = _b * STG_BYTES; \
        cpasync16(aD0 + _o, aS0 + _k); \
        cpasync16(aD1 + _o, aS1 + _k); \
        cpasync16(bD0 + _o, bS0 + _k); \
        cpasync16(bD1 + _o, bS1 + _k); \
        CP_COMMIT(); \
    } while (0)

    const int wm = (wid & 3) * 32;
    const int wn = (wid >> 2) * 64;
    const int g  = lane >> 2, tg = lane & 3;

    float acc[2][8][4];
    #pragma unroll
    for (int i = 0; i < 2; i++)
        #pragma unroll
        for (int j = 0; j < 8; j++)
            #pragma unroll
            for (int q = 0; q < 4; q++) acc[i][j][q] = 0.f;

    const int NSTG = KDIM / KSTG;
    PRODUCE(0); PRODUCE(1); PRODUCE(2);

    for (int s = 0; s < NSTG; s++) {
        if (s + NSTAGE - 1 < NSTG) PRODUCE(s + NSTAGE - 1);
        else CP_COMMIT();                      // keep group accounting uniform
        CP_WAIT(NSTAGE - 1);
        __syncthreads();

        const int buf = s & (NSTAGE - 1);
        const unsigned int* Ab = Asm + buf * (STG_BYTES / 4);
        const unsigned int* Bb = Bsm + buf * (STG_BYTES / 4);

        uint4 aF[2][2];
        #pragma unroll
        for (int i = 0; i < 2; i++) {
            const int r1 = wm + i * 16 + g;
            aF[i][0] = *(const uint4*)(Ab + r1 * 16 + tg * 4);
            aF[i][1] = *(const uint4*)(Ab + (r1 + 8) * 16 + tg * 4);
        }
        #pragma unroll
        for (int j = 0; j < 8; j++) {
            const int nb = wn + j * 8 + g;
            uint4 bF = *(const uint4*)(Bb + nb * 16 + tg * 4);
            #pragma unroll
            for (int i = 0; i < 2; i++) {
                mma_tf32(acc[i][j], aF[i][0].x, aF[i][1].x, aF[i][0].y, aF[i][1].y,
                         bF.x, bF.y);
                mma_tf32(acc[i][j], aF[i][0].z, aF[i][1].z, aF[i][0].w, aF[i][1].w,
                         bF.z, bF.w);
            }
        }
        __syncthreads();
    }

    // -------- epilogue --------
    #pragma unroll
    for (int i = 0; i < 2; i++) {
        #pragma unroll
        for (int half = 0; half < 2; half++) {
            const int r = wm + i * 16 + g + half * 8;
            if (FFN1) {
                float* hrow = g_H + (size_t)(hbase + r) * HDIM;
                #pragma unroll
                for (int j = 0; j < 8; j++) {
                    const int n = n0 + wn + j * 8 + tg * 2;
                    float2 v;
                    v.x = rna_tf32(gelu_tanh(acc[i][j][half * 2 + 0] + be[n]));
                    v.y = rna_tf32(gelu_tanh(acc[i][j][half * 2 + 1] + be[n + 1]));
                    *(float2*)(hrow + n) = v;
                }
            } else if (r < valid) {
                const int tok = tok_s[r];
                const float w = wt_s[r];
                float* orow = outp + (size_t)tok * CDIM;
                #pragma unroll
                for (int j = 0; j < 8; j++) {
                    const int n = n0 + wn + j * 8 + tg * 2;
                    atomicAdd(orow + n,     w * (acc[i][j][half * 2 + 0] + be[n]));
                    atomicAdd(orow + n + 1, w * (acc[i][j][half * 2 + 1] + be[n + 1]));
                }
            }
        }
    }
    #undef PRODUCE
}

// ---------------- launch ----------------
extern "C" void kernel_launch(void* const* d_in, const int* in_sizes, int n_in,
                              void* d_out, int out_size) {
    const float* x  = (const float*)d_in[0];
    const float* gw = (const float*)d_in[1];
    const float* w1 = (const float*)d_in[2];
    const float* b1 = (const float*)d_in[3];
    const float* w2 = (const float*)d_in[4];
    const float* b2 = (const float*)d_in[5];
    float* out = (float*)d_out;

    cudaFuncSetAttribute(ffn_gemm<CDIM, true >, cudaFuncAttributeMaxDynamicSharedMemorySize, FFN_SMEM);
    cudaFuncSetAttribute(ffn_gemm<HDIM, false>, cudaFuncAttributeMaxDynamicSharedMemorySize, FFN_SMEM);

    cudaMemsetAsync(out, 0, (size_t)T_TOK * CDIM * sizeof(float));
    reset_kernel<<<1, 32>>>();
    router_kernel<<<T_TOK, 256>>>(x, gw);
    sched_kernel<<<1, 32>>>();
    convw1_kernel<<<(NEXP * HDIM * CDIM) / 1024, 256>>>(w1);
    convw2_kernel<<<(NEXP * CDIM * HDIM) / 1024, 256>>>(w2);
    gather_kernel<<<MAXTILES * TM, 256>>>(x);
    ffn_gemm<CDIM, true ><<<dim3(MAXTILES, HDIM / 128), 256, FFN_SMEM>>>(b1, nullptr);
    ffn_gemm<HDIM, false><<<dim3(MAXTILES, CDIM / 128), 256, FFN_SMEM>>>(b2, out);
}